// round 10
// baseline (speedup 1.0000x reference)
#include <cuda_runtime.h>
#include <math.h>
#include <stdint.h>

#define BB 2
#define SS 4096
#define DD 768
#define HH 12
#define DHD 64
#define NROW (BB*SS)

// Scratch for projected Q/K/V: [B,H,S,DH] each, fp32.
__device__ float g_q[(size_t)BB*HH*SS*DHD];
__device__ float g_k[(size_t)BB*HH*SS*DHD];
__device__ float g_v[(size_t)BB*HH*SS*DHD];

__device__ __forceinline__ uint32_t f2tf(float x) {
    uint32_t r;
    asm("cvt.rna.tf32.f32 %0, %1;" : "=r"(r) : "f"(x));
    return r;
}

__device__ __forceinline__ void mma_tf32(float c[4], const uint32_t a[4],
                                         uint32_t b0, uint32_t b1) {
    asm volatile(
        "mma.sync.aligned.m16n8k8.row.col.f32.tf32.tf32.f32 "
        "{%0,%1,%2,%3}, {%4,%5,%6,%7}, {%8,%9}, {%0,%1,%2,%3};\n"
        : "+f"(c[0]), "+f"(c[1]), "+f"(c[2]), "+f"(c[3])
        : "r"(a[0]), "r"(a[1]), "r"(a[2]), "r"(a[3]), "r"(b0), "r"(b1));
}

__device__ __forceinline__ void cpasync16(uint32_t smem_addr, const void* gptr) {
    asm volatile("cp.async.cg.shared.global [%0], [%1], 16;\n"
                 :: "r"(smem_addr), "l"(gptr));
}

// ---------------------------------------------------------------------------
// QKV projection, tensor pipe, 3xTF32 split mma.
// Hi/lo tf32 split done ONCE at staging time into smem; inner loop is pure
// conflict-free LDS + MMA (no ALU on the MMA dependency path).
// Dynamic smem 72 KB. Block 128 threads (4 warps x 16 rows), grid (NROW/64, H).
// ---------------------------------------------------------------------------
#define XSTR 36
#define WSTR 72
#define PROJ_SMEM_BYTES ((2 * 64 * XSTR + 6 * 32 * WSTR) * 4)

__global__ __launch_bounds__(128)
void qkv_proj_tc_kernel(const float* __restrict__ x,
                        const float* __restrict__ Wq,
                        const float* __restrict__ Wk,
                        const float* __restrict__ Wv) {
    extern __shared__ __align__(16) uint32_t psm[];
    uint32_t* sXh = psm;                         // [64][XSTR]
    uint32_t* sXl = sXh + 64 * XSTR;
    uint32_t* swh[3];
    uint32_t* swl[3];
    swh[0] = sXl + 64 * XSTR;
    swh[1] = swh[0] + 32 * WSTR;
    swh[2] = swh[1] + 32 * WSTR;
    swl[0] = swh[2] + 32 * WSTR;
    swl[1] = swl[0] + 32 * WSTR;
    swl[2] = swl[1] + 32 * WSTR;

    const int t    = threadIdx.x;
    const int w    = t >> 5;
    const int lane = t & 31;
    const int g    = lane >> 2;
    const int lt   = lane & 3;

    const int h  = blockIdx.y;
    const int m0 = blockIdx.x * 64;

    const float* wsrc[3] = { Wq + (size_t)h * DD * DHD,
                             Wk + (size_t)h * DD * DHD,
                             Wv + (size_t)h * DD * DHD };

    float acc[3][8][4];
    #pragma unroll
    for (int m = 0; m < 3; m++)
        #pragma unroll
        for (int nt = 0; nt < 8; nt++)
            #pragma unroll
            for (int i = 0; i < 4; i++) acc[m][nt][i] = 0.0f;

    const int rA0 = (w * 16 + g) * XSTR;
    const int rA1 = (w * 16 + g + 8) * XSTR;

    for (int k0 = 0; k0 < DD; k0 += 32) {
        __syncthreads();
        // ---- stage X tile 64x32, pre-split hi/lo ----
        #pragma unroll
        for (int i = 0; i < 4; i++) {
            int idx  = t + i * 128;
            int row  = idx >> 3;
            int col4 = (idx & 7) * 4;
            float4 xv = *(const float4*)&x[(size_t)(m0 + row) * DD + k0 + col4];
            uint4 hi, lo;
            hi.x = f2tf(xv.x); lo.x = f2tf(xv.x - __uint_as_float(hi.x));
            hi.y = f2tf(xv.y); lo.y = f2tf(xv.y - __uint_as_float(hi.y));
            hi.z = f2tf(xv.z); lo.z = f2tf(xv.z - __uint_as_float(hi.z));
            hi.w = f2tf(xv.w); lo.w = f2tf(xv.w - __uint_as_float(hi.w));
            *(uint4*)&sXh[row * XSTR + col4] = hi;
            *(uint4*)&sXl[row * XSTR + col4] = lo;
        }
        // ---- stage W tiles 32x64 x3, pre-split hi/lo ----
        #pragma unroll
        for (int m = 0; m < 3; m++) {
            #pragma unroll
            for (int i = 0; i < 4; i++) {
                int idx  = t + i * 128;
                int row  = idx >> 4;
                int col4 = (idx & 15) * 4;
                float4 wv = *(const float4*)&wsrc[m][(size_t)(k0 + row) * DHD + col4];
                uint4 hi, lo;
                hi.x = f2tf(wv.x); lo.x = f2tf(wv.x - __uint_as_float(hi.x));
                hi.y = f2tf(wv.y); lo.y = f2tf(wv.y - __uint_as_float(hi.y));
                hi.z = f2tf(wv.z); lo.z = f2tf(wv.z - __uint_as_float(hi.z));
                hi.w = f2tf(wv.w); lo.w = f2tf(wv.w - __uint_as_float(hi.w));
                *(uint4*)&swh[m][row * WSTR + col4] = hi;
                *(uint4*)&swl[m][row * WSTR + col4] = lo;
            }
        }
        __syncthreads();

        #pragma unroll 1
        for (int slab = 0; slab < 4; slab++) {
            int ca = slab * 8 + lt;
            uint32_t Ah[4], Al[4];
            Ah[0] = sXh[rA0 + ca];     Al[0] = sXl[rA0 + ca];
            Ah[1] = sXh[rA1 + ca];     Al[1] = sXl[rA1 + ca];
            Ah[2] = sXh[rA0 + ca + 4]; Al[2] = sXl[rA0 + ca + 4];
            Ah[3] = sXh[rA1 + ca + 4]; Al[3] = sXl[rA1 + ca + 4];

            const int rb0 = (slab * 8 + lt) * WSTR + g;
            const int rb1 = rb0 + 4 * WSTR;
            #pragma unroll
            for (int nt = 0; nt < 8; nt++) {
                #pragma unroll
                for (int m = 0; m < 3; m++) {
                    uint32_t bh0 = swh[m][rb0 + nt * 8];
                    uint32_t bh1 = swh[m][rb1 + nt * 8];
                    uint32_t bl0 = swl[m][rb0 + nt * 8];
                    uint32_t bl1 = swl[m][rb1 + nt * 8];
                    mma_tf32(acc[m][nt], Ah, bh0, bh1);
                    mma_tf32(acc[m][nt], Ah, bl0, bl1);
                    mma_tf32(acc[m][nt], Al, bh0, bh1);
                }
            }
        }
    }

    const int b  = m0 / SS;
    const int s0 = m0 % SS;
    const size_t ob = ((size_t)(b * HH + h) * SS + s0 + w * 16) * DHD;
    float* outs[3] = { g_q, g_k, g_v };
    #pragma unroll
    for (int m = 0; m < 3; m++) {
        float* op = outs[m] + ob;
        #pragma unroll
        for (int nt = 0; nt < 8; nt++) {
            int e = nt * 8 + 2 * lt;
            *(float2*)&op[(size_t)g * DHD + e] =
                make_float2(acc[m][nt][0], acc[m][nt][1]);
            *(float2*)&op[(size_t)(g + 8) * DHD + e] =
                make_float2(acc[m][nt][2], acc[m][nt][3]);
        }
    }
}

// ---------------------------------------------------------------------------
// Flash attention, mma.sync tf32, M=32/warp (Q tile 128 rows, 4 warps).
// K/V: raw fp32 staged via cp.async, double-buffered (prefetch j+1 during
// compute of j); mma reads raw fp32 bits as tf32 (truncation). Q and P keep
// RNA tf32 conversion.
// ---------------------------------------------------------------------------
#define KSTR 68
#define VSTR 72
#define TILE_U (64 * KSTR + 64 * VSTR)
#define ATT_SMEM_BYTES (2 * TILE_U * 4)

__device__ __forceinline__ void stage_tile_async(uint32_t sbase_bytes,
                                                 const float* kp,
                                                 const float* vp, int t) {
    #pragma unroll
    for (int i = 0; i < 8; i++) {
        int idx  = t + i * 128;
        int row  = idx >> 4;
        int col4 = (idx & 15) * 4;
        uint32_t kdst = sbase_bytes + (uint32_t)(row * KSTR + col4) * 4u;
        uint32_t vdst = sbase_bytes + (uint32_t)(64 * KSTR + row * VSTR + col4) * 4u;
        cpasync16(kdst, kp + (size_t)row * DHD + col4);
        cpasync16(vdst, vp + (size_t)row * DHD + col4);
    }
}

__global__ __launch_bounds__(128, 2)
void flash_attn_tc_kernel(float* __restrict__ out) {
    extern __shared__ __align__(16) uint32_t smem_u[];

    const int t    = threadIdx.x;
    const int w    = t >> 5;
    const int lane = t & 31;
    const int g    = lane >> 2;
    const int lt   = lane & 3;

    const int bh = blockIdx.y;
    const int b  = bh / HH;
    const int h  = bh % HH;
    const int qi = gridDim.x - 1 - blockIdx.x;   // heavy blocks first
    const int q0 = qi * 128;

    const float* qp    = g_q + ((size_t)bh * SS + q0 + w * 32) * DHD;
    const float* kbase = g_k + (size_t)bh * SS * DHD;
    const float* vbase = g_v + (size_t)bh * SS * DHD;

    const uint32_t sbase = (uint32_t)__cvta_generic_to_shared(smem_u);

    // Q fragments: 2 m-tiles x 8 dh-slabs x 4 regs, loaded once, RNA tf32.
    uint32_t Qa[2][8][4];
    #pragma unroll
    for (int u = 0; u < 2; u++) {
        #pragma unroll
        for (int kk = 0; kk < 8; kk++) {
            int c = kk * 8 + lt;
            Qa[u][kk][0] = f2tf(qp[(size_t)(u * 16 + g) * DHD + c]);
            Qa[u][kk][1] = f2tf(qp[(size_t)(u * 16 + g + 8) * DHD + c]);
            Qa[u][kk][2] = f2tf(qp[(size_t)(u * 16 + g) * DHD + c + 4]);
            Qa[u][kk][3] = f2tf(qp[(size_t)(u * 16 + g + 8) * DHD + c + 4]);
        }
    }

    float mr[2][2], lr[2][2];
    #pragma unroll
    for (int u = 0; u < 2; u++) {
        mr[u][0] = -INFINITY; mr[u][1] = -INFINITY;
        lr[u][0] = 0.0f;      lr[u][1] = 0.0f;
    }
    float O[2][8][4];
    #pragma unroll
    for (int u = 0; u < 2; u++)
        #pragma unroll
        for (int nt = 0; nt < 8; nt++)
            #pragma unroll
            for (int i = 0; i < 4; i++) O[u][nt][i] = 0.0f;

    const int srcA = (lane & 28) | (lt >> 1);
    const int srcB = srcA + 2;
    const int par  = lt & 1;

    const int jmax = 2 * qi + 1;

    // Prologue: prefetch tile 0 into buffer 0.
    stage_tile_async(sbase, kbase, vbase, t);
    asm volatile("cp.async.commit_group;\n" ::: "memory");

    for (int j = 0; j <= jmax; j++) {
        const int cur = j & 1;
        if (j < jmax) {
            stage_tile_async(sbase + (uint32_t)((j + 1) & 1) * TILE_U * 4u,
                             kbase + (size_t)(j + 1) * 64 * DHD,
                             vbase + (size_t)(j + 1) * 64 * DHD, t);
            asm volatile("cp.async.commit_group;\n" ::: "memory");
            asm volatile("cp.async.wait_group 1;\n" ::: "memory");
        } else {
            asm volatile("cp.async.wait_group 0;\n" ::: "memory");
        }
        __syncthreads();   // tile j visible to all threads

        const uint32_t* sK = smem_u + cur * TILE_U;
        const uint32_t* sV = sK + 64 * KSTR;

        // ---- S = Q K^T : raw fp32 B-fragments (tf32 truncation) ----
        float S[2][8][4];
        #pragma unroll
        for (int u = 0; u < 2; u++)
            #pragma unroll
            for (int nt = 0; nt < 8; nt++)
                #pragma unroll
                for (int i = 0; i < 4; i++) S[u][nt][i] = 0.0f;
        #pragma unroll
        for (int kk = 0; kk < 8; kk++) {
            #pragma unroll
            for (int nt = 0; nt < 8; nt++) {
                const uint32_t* krow = &sK[(nt * 8 + g) * KSTR + kk * 8 + lt];
                uint32_t b0 = krow[0];
                uint32_t b1 = krow[4];
                mma_tf32(S[0][nt], Qa[0][kk], b0, b1);
                mma_tf32(S[1][nt], Qa[1][kk], b0, b1);
            }
        }

        // ---- scale + causal mask + online softmax per m-tile ----
        const float scale = 0.125f;
        uint32_t Ptf[2][8][4];
        #pragma unroll
        for (int u = 0; u < 2; u++) {
            const int r0 = q0 + w * 32 + u * 16 + g;
            const int r1 = r0 + 8;
            #pragma unroll
            for (int nt = 0; nt < 8; nt++) {
                #pragma unroll
                for (int i = 0; i < 4; i++) S[u][nt][i] *= scale;
            }
            if (j * 64 + 63 > q0 + w * 32 + u * 16) {
                #pragma unroll
                for (int nt = 0; nt < 8; nt++) {
                    int col = j * 64 + nt * 8 + 2 * lt;
                    if (col     > r0) S[u][nt][0] = -INFINITY;
                    if (col + 1 > r0) S[u][nt][1] = -INFINITY;
                    if (col     > r1) S[u][nt][2] = -INFINITY;
                    if (col + 1 > r1) S[u][nt][3] = -INFINITY;
                }
            }

            float mx0 = -INFINITY, mx1 = -INFINITY;
            #pragma unroll
            for (int nt = 0; nt < 8; nt++) {
                mx0 = fmaxf(mx0, fmaxf(S[u][nt][0], S[u][nt][1]));
                mx1 = fmaxf(mx1, fmaxf(S[u][nt][2], S[u][nt][3]));
            }
            mx0 = fmaxf(mx0, __shfl_xor_sync(0xffffffffu, mx0, 1));
            mx0 = fmaxf(mx0, __shfl_xor_sync(0xffffffffu, mx0, 2));
            mx1 = fmaxf(mx1, __shfl_xor_sync(0xffffffffu, mx1, 1));
            mx1 = fmaxf(mx1, __shfl_xor_sync(0xffffffffu, mx1, 2));
            float mn0 = fmaxf(mr[u][0], mx0);
            float mn1 = fmaxf(mr[u][1], mx1);
            float f0 = __expf(mr[u][0] - mn0);
            float f1 = __expf(mr[u][1] - mn1);
            mr[u][0] = mn0; mr[u][1] = mn1;

            float ps0 = 0.0f, ps1 = 0.0f;
            #pragma unroll
            for (int nt = 0; nt < 8; nt++) {
                float p0 = __expf(S[u][nt][0] - mn0);
                float p1 = __expf(S[u][nt][1] - mn0);
                float p2 = __expf(S[u][nt][2] - mn1);
                float p3 = __expf(S[u][nt][3] - mn1);
                ps0 += p0 + p1;
                ps1 += p2 + p3;
                Ptf[u][nt][0] = f2tf(p0); Ptf[u][nt][1] = f2tf(p1);
                Ptf[u][nt][2] = f2tf(p2); Ptf[u][nt][3] = f2tf(p3);
            }
            ps0 += __shfl_xor_sync(0xffffffffu, ps0, 1);
            ps0 += __shfl_xor_sync(0xffffffffu, ps0, 2);
            ps1 += __shfl_xor_sync(0xffffffffu, ps1, 1);
            ps1 += __shfl_xor_sync(0xffffffffu, ps1, 2);
            lr[u][0] = lr[u][0] * f0 + ps0;
            lr[u][1] = lr[u][1] * f1 + ps1;

            #pragma unroll
            for (int nt = 0; nt < 8; nt++) {
                O[u][nt][0] *= f0; O[u][nt][1] *= f0;
                O[u][nt][2] *= f1; O[u][nt][3] *= f1;
            }
        }

        // ---- O += P @ V : raw fp32 V fragments ----
        #pragma unroll
        for (int kt = 0; kt < 8; kt++) {
            uint32_t A[2][4];
            #pragma unroll
            for (int u = 0; u < 2; u++) {
                uint32_t pa0 = __shfl_sync(0xffffffffu, Ptf[u][kt][0], srcA);
                uint32_t pa1 = __shfl_sync(0xffffffffu, Ptf[u][kt][1], srcA);
                uint32_t pa2 = __shfl_sync(0xffffffffu, Ptf[u][kt][2], srcA);
                uint32_t pa3 = __shfl_sync(0xffffffffu, Ptf[u][kt][3], srcA);
                uint32_t pb0 = __shfl_sync(0xffffffffu, Ptf[u][kt][0], srcB);
                uint32_t pb1 = __shfl_sync(0xffffffffu, Ptf[u][kt][1], srcB);
                uint32_t pb2 = __shfl_sync(0xffffffffu, Ptf[u][kt][2], srcB);
                uint32_t pb3 = __shfl_sync(0xffffffffu, Ptf[u][kt][3], srcB);
                A[u][0] = par ? pa1 : pa0;
                A[u][1] = par ? pa3 : pa2;
                A[u][2] = par ? pb1 : pb0;
                A[u][3] = par ? pb3 : pb2;
            }
            const uint32_t* vrow0 = &sV[(kt * 8 + lt) * VSTR + g];
            const uint32_t* vrow1 = &sV[(kt * 8 + lt + 4) * VSTR + g];
            #pragma unroll
            for (int nt = 0; nt < 8; nt++) {
                uint32_t b0 = vrow0[nt * 8];
                uint32_t b1 = vrow1[nt * 8];
                mma_tf32(O[0][nt], A[0], b0, b1);
                mma_tf32(O[1][nt], A[1], b0, b1);
            }
        }
        __syncthreads();   // all done reading tile j before it is overwritten
    }

    // ---- write output ----
    #pragma unroll
    for (int u = 0; u < 2; u++) {
        const int r0 = q0 + w * 32 + u * 16 + g;
        const int r1 = r0 + 8;
        float inv0 = 1.0f / lr[u][0];
        float inv1 = 1.0f / lr[u][1];
        #pragma unroll
        for (int nt = 0; nt < 8; nt++) {
            int e = h * DHD + nt * 8 + 2 * lt;
            size_t o0 = ((size_t)b * SS + r0) * (HH * DHD) + e;
            size_t o1 = ((size_t)b * SS + r1) * (HH * DHD) + e;
            *(float2*)&out[o0] = make_float2(O[u][nt][0] * inv0, O[u][nt][1] * inv0);
            *(float2*)&out[o1] = make_float2(O[u][nt][2] * inv1, O[u][nt][3] * inv1);
        }
    }
}

extern "C" void kernel_launch(void* const* d_in, const int* in_sizes, int n_in,
                              void* d_out, int out_size) {
    const float* x  = (const float*)d_in[0];
    const float* Wq = (const float*)d_in[1];
    const float* Wk = (const float*)d_in[2];
    const float* Wv = (const float*)d_in[3];
    float* out = (float*)d_out;

    cudaFuncSetAttribute(qkv_proj_tc_kernel,
                         cudaFuncAttributeMaxDynamicSharedMemorySize,
                         PROJ_SMEM_BYTES);
    cudaFuncSetAttribute(flash_attn_tc_kernel,
                         cudaFuncAttributeMaxDynamicSharedMemorySize,
                         ATT_SMEM_BYTES);

    qkv_proj_tc_kernel<<<dim3(NROW / 64, HH), 128, PROJ_SMEM_BYTES>>>(x, Wq, Wk, Wv);
    flash_attn_tc_kernel<<<dim3(SS / 128, BB * HH), 128, ATT_SMEM_BYTES>>>(out);
}

// round 11
// speedup vs baseline: 1.0688x; 1.0688x over previous
#include <cuda_runtime.h>
#include <math.h>
#include <stdint.h>

#define BB 2
#define SS 4096
#define DD 768
#define HH 12
#define DHD 64
#define NROW (BB*SS)

// Scratch for projected Q/K/V: [B,H,S,DH] each, fp32.
__device__ float g_q[(size_t)BB*HH*SS*DHD];
__device__ float g_k[(size_t)BB*HH*SS*DHD];
__device__ float g_v[(size_t)BB*HH*SS*DHD];

__device__ __forceinline__ uint32_t f2tf(float x) {
    uint32_t r;
    asm("cvt.rna.tf32.f32 %0, %1;" : "=r"(r) : "f"(x));
    return r;
}

__device__ __forceinline__ void mma_tf32(float c[4], const uint32_t a[4],
                                         uint32_t b0, uint32_t b1) {
    asm volatile(
        "mma.sync.aligned.m16n8k8.row.col.f32.tf32.tf32.f32 "
        "{%0,%1,%2,%3}, {%4,%5,%6,%7}, {%8,%9}, {%0,%1,%2,%3};\n"
        : "+f"(c[0]), "+f"(c[1]), "+f"(c[2]), "+f"(c[3])
        : "r"(a[0]), "r"(a[1]), "r"(a[2]), "r"(a[3]), "r"(b0), "r"(b1));
}

__device__ __forceinline__ void cpasync16(uint32_t smem_addr, const void* gptr) {
    asm volatile("cp.async.cg.shared.global [%0], [%1], 16;\n"
                 :: "r"(smem_addr), "l"(gptr));
}

// ---------------------------------------------------------------------------
// QKV projection, tensor pipe, 3xTF32 split mma (R4 inner loop: fp32 smem,
// on-the-fly hi/lo split) + cp.async double-buffered staging.
// Block 128 threads (4 warps x 16 rows), grid (NROW/64, H).
// Dynamic smem: 2 x (X 64x36 + 3 x W 32x72) fp32 = 73.7 KB.
// ---------------------------------------------------------------------------
#define XSTR 36
#define WSTR 72
#define PTILE_U (64 * XSTR + 3 * 32 * WSTR)       // floats per buffer = 9216
#define PROJ_SMEM_BYTES (2 * PTILE_U * 4)

__device__ __forceinline__ void proj_stage_async(uint32_t sbase_bytes,
                                                 const float* xp,
                                                 const float* w0,
                                                 const float* w1,
                                                 const float* w2,
                                                 int k0, int t) {
    // X tile 64x32: 512 float4
    #pragma unroll
    for (int i = 0; i < 4; i++) {
        int idx  = t + i * 128;
        int row  = idx >> 3;
        int col4 = (idx & 7) * 4;
        cpasync16(sbase_bytes + (uint32_t)(row * XSTR + col4) * 4u,
                  xp + (size_t)row * DD + k0 + col4);
    }
    // W tiles 32x64 x3: 512 float4 each
    const uint32_t woff = 64 * XSTR;
    #pragma unroll
    for (int i = 0; i < 4; i++) {
        int idx  = t + i * 128;
        int row  = idx >> 4;
        int col4 = (idx & 15) * 4;
        size_t go = (size_t)(k0 + row) * DHD + col4;
        uint32_t so = (uint32_t)(row * WSTR + col4);
        cpasync16(sbase_bytes + (woff + so) * 4u,                 w0 + go);
        cpasync16(sbase_bytes + (woff + 32 * WSTR + so) * 4u,     w1 + go);
        cpasync16(sbase_bytes + (woff + 2 * 32 * WSTR + so) * 4u, w2 + go);
    }
}

__global__ __launch_bounds__(128)
void qkv_proj_tc_kernel(const float* __restrict__ x,
                        const float* __restrict__ Wq,
                        const float* __restrict__ Wk,
                        const float* __restrict__ Wv) {
    extern __shared__ __align__(16) float psm[];

    const int t    = threadIdx.x;
    const int w    = t >> 5;
    const int lane = t & 31;
    const int g    = lane >> 2;
    const int lt   = lane & 3;

    const int h  = blockIdx.y;
    const int m0 = blockIdx.x * 64;

    const float* xp  = x + (size_t)m0 * DD;
    const float* wqp = Wq + (size_t)h * DD * DHD;
    const float* wkp = Wk + (size_t)h * DD * DHD;
    const float* wvp = Wv + (size_t)h * DD * DHD;

    const uint32_t sbase = (uint32_t)__cvta_generic_to_shared(psm);

    float acc[3][8][4];
    #pragma unroll
    for (int m = 0; m < 3; m++)
        #pragma unroll
        for (int nt = 0; nt < 8; nt++)
            #pragma unroll
            for (int i = 0; i < 4; i++) acc[m][nt][i] = 0.0f;

    const int rA0 = (w * 16 + g) * XSTR;
    const int rA1 = (w * 16 + g + 8) * XSTR;

    // Prologue: stage k-step 0 into buffer 0.
    proj_stage_async(sbase, xp, wqp, wkp, wvp, 0, t);
    asm volatile("cp.async.commit_group;\n" ::: "memory");

    const int NSTEP = DD / 32;   // 24
    for (int ks = 0; ks < NSTEP; ks++) {
        const int cur = ks & 1;
        if (ks + 1 < NSTEP) {
            proj_stage_async(sbase + (uint32_t)((ks + 1) & 1) * PTILE_U * 4u,
                             xp, wqp, wkp, wvp, (ks + 1) * 32, t);
            asm volatile("cp.async.commit_group;\n" ::: "memory");
            asm volatile("cp.async.wait_group 1;\n" ::: "memory");
        } else {
            asm volatile("cp.async.wait_group 0;\n" ::: "memory");
        }
        __syncthreads();

        const float* sX = psm + cur * PTILE_U;
        const float* sW[3] = { sX + 64 * XSTR,
                               sX + 64 * XSTR + 32 * WSTR,
                               sX + 64 * XSTR + 2 * 32 * WSTR };

        #pragma unroll 1
        for (int slab = 0; slab < 4; slab++) {
            int ca = slab * 8 + lt;
            float x0 = sX[rA0 + ca];
            float x1 = sX[rA1 + ca];
            float x2 = sX[rA0 + ca + 4];
            float x3 = sX[rA1 + ca + 4];
            uint32_t Ah[4], Al[4];
            Ah[0] = f2tf(x0); Al[0] = f2tf(x0 - __uint_as_float(Ah[0]));
            Ah[1] = f2tf(x1); Al[1] = f2tf(x1 - __uint_as_float(Ah[1]));
            Ah[2] = f2tf(x2); Al[2] = f2tf(x2 - __uint_as_float(Ah[2]));
            Ah[3] = f2tf(x3); Al[3] = f2tf(x3 - __uint_as_float(Ah[3]));

            const int rb0 = (slab * 8 + lt) * WSTR + g;
            const int rb1 = rb0 + 4 * WSTR;
            #pragma unroll
            for (int nt = 0; nt < 8; nt++) {
                #pragma unroll
                for (int m = 0; m < 3; m++) {
                    float b0f = sW[m][rb0 + nt * 8];
                    float b1f = sW[m][rb1 + nt * 8];
                    uint32_t bh0 = f2tf(b0f), bh1 = f2tf(b1f);
                    uint32_t bl0 = f2tf(b0f - __uint_as_float(bh0));
                    uint32_t bl1 = f2tf(b1f - __uint_as_float(bh1));
                    mma_tf32(acc[m][nt], Ah, bh0, bh1);
                    mma_tf32(acc[m][nt], Ah, bl0, bl1);
                    mma_tf32(acc[m][nt], Al, bh0, bh1);
                }
            }
        }
        __syncthreads();   // done reading cur before it is restaged
    }

    const int b  = m0 / SS;
    const int s0 = m0 % SS;
    const size_t ob = ((size_t)(b * HH + h) * SS + s0 + w * 16) * DHD;
    float* outs[3] = { g_q, g_k, g_v };
    #pragma unroll
    for (int m = 0; m < 3; m++) {
        float* op = outs[m] + ob;
        #pragma unroll
        for (int nt = 0; nt < 8; nt++) {
            int e = nt * 8 + 2 * lt;
            *(float2*)&op[(size_t)g * DHD + e] =
                make_float2(acc[m][nt][0], acc[m][nt][1]);
            *(float2*)&op[(size_t)(g + 8) * DHD + e] =
                make_float2(acc[m][nt][2], acc[m][nt][3]);
        }
    }
}

// ---------------------------------------------------------------------------
// Flash attention (R10 structure): mma.sync tf32, M=32/warp, cp.async
// double-buffered raw fp32 K/V (tf32 truncation), register softmax.
// R11 tweak: log2e folded into scale, exp2f instead of __expf.
// ---------------------------------------------------------------------------
#define KSTR 68
#define VSTR 72
#define TILE_U (64 * KSTR + 64 * VSTR)
#define ATT_SMEM_BYTES (2 * TILE_U * 4)

__device__ __forceinline__ void stage_tile_async(uint32_t sbase_bytes,
                                                 const float* kp,
                                                 const float* vp, int t) {
    #pragma unroll
    for (int i = 0; i < 8; i++) {
        int idx  = t + i * 128;
        int row  = idx >> 4;
        int col4 = (idx & 15) * 4;
        uint32_t kdst = sbase_bytes + (uint32_t)(row * KSTR + col4) * 4u;
        uint32_t vdst = sbase_bytes + (uint32_t)(64 * KSTR + row * VSTR + col4) * 4u;
        cpasync16(kdst, kp + (size_t)row * DHD + col4);
        cpasync16(vdst, vp + (size_t)row * DHD + col4);
    }
}

__global__ __launch_bounds__(128, 2)
void flash_attn_tc_kernel(float* __restrict__ out) {
    extern __shared__ __align__(16) uint32_t smem_u[];

    const int t    = threadIdx.x;
    const int w    = t >> 5;
    const int lane = t & 31;
    const int g    = lane >> 2;
    const int lt   = lane & 3;

    const int bh = blockIdx.y;
    const int b  = bh / HH;
    const int h  = bh % HH;
    const int qi = gridDim.x - 1 - blockIdx.x;   // heavy blocks first
    const int q0 = qi * 128;

    const float* qp    = g_q + ((size_t)bh * SS + q0 + w * 32) * DHD;
    const float* kbase = g_k + (size_t)bh * SS * DHD;
    const float* vbase = g_v + (size_t)bh * SS * DHD;

    const uint32_t sbase = (uint32_t)__cvta_generic_to_shared(smem_u);

    // Q fragments: 2 m-tiles x 8 dh-slabs x 4 regs, loaded once, RNA tf32.
    uint32_t Qa[2][8][4];
    #pragma unroll
    for (int u = 0; u < 2; u++) {
        #pragma unroll
        for (int kk = 0; kk < 8; kk++) {
            int c = kk * 8 + lt;
            Qa[u][kk][0] = f2tf(qp[(size_t)(u * 16 + g) * DHD + c]);
            Qa[u][kk][1] = f2tf(qp[(size_t)(u * 16 + g + 8) * DHD + c]);
            Qa[u][kk][2] = f2tf(qp[(size_t)(u * 16 + g) * DHD + c + 4]);
            Qa[u][kk][3] = f2tf(qp[(size_t)(u * 16 + g + 8) * DHD + c + 4]);
        }
    }

    float mr[2][2], lr[2][2];
    #pragma unroll
    for (int u = 0; u < 2; u++) {
        mr[u][0] = -INFINITY; mr[u][1] = -INFINITY;
        lr[u][0] = 0.0f;      lr[u][1] = 0.0f;
    }
    float O[2][8][4];
    #pragma unroll
    for (int u = 0; u < 2; u++)
        #pragma unroll
        for (int nt = 0; nt < 8; nt++)
            #pragma unroll
            for (int i = 0; i < 4; i++) O[u][nt][i] = 0.0f;

    const int srcA = (lane & 28) | (lt >> 1);
    const int srcB = srcA + 2;
    const int par  = lt & 1;

    const int jmax = 2 * qi + 1;

    stage_tile_async(sbase, kbase, vbase, t);
    asm volatile("cp.async.commit_group;\n" ::: "memory");

    for (int j = 0; j <= jmax; j++) {
        const int cur = j & 1;
        if (j < jmax) {
            stage_tile_async(sbase + (uint32_t)((j + 1) & 1) * TILE_U * 4u,
                             kbase + (size_t)(j + 1) * 64 * DHD,
                             vbase + (size_t)(j + 1) * 64 * DHD, t);
            asm volatile("cp.async.commit_group;\n" ::: "memory");
            asm volatile("cp.async.wait_group 1;\n" ::: "memory");
        } else {
            asm volatile("cp.async.wait_group 0;\n" ::: "memory");
        }
        __syncthreads();

        const uint32_t* sK = smem_u + cur * TILE_U;
        const uint32_t* sV = sK + 64 * KSTR;

        // ---- S = Q K^T : raw fp32 B-fragments (tf32 truncation) ----
        float S[2][8][4];
        #pragma unroll
        for (int u = 0; u < 2; u++)
            #pragma unroll
            for (int nt = 0; nt < 8; nt++)
                #pragma unroll
                for (int i = 0; i < 4; i++) S[u][nt][i] = 0.0f;
        #pragma unroll
        for (int kk = 0; kk < 8; kk++) {
            #pragma unroll
            for (int nt = 0; nt < 8; nt++) {
                const uint32_t* krow = &sK[(nt * 8 + g) * KSTR + kk * 8 + lt];
                uint32_t b0 = krow[0];
                uint32_t b1 = krow[4];
                mma_tf32(S[0][nt], Qa[0][kk], b0, b1);
                mma_tf32(S[1][nt], Qa[1][kk], b0, b1);
            }
        }

        // ---- scale (log2 domain) + causal mask + online softmax ----
        const float scale = 0.125f * 1.44269504089f;   // 1/sqrt(64) * log2(e)
        uint32_t Ptf[2][8][4];
        #pragma unroll
        for (int u = 0; u < 2; u++) {
            const int r0 = q0 + w * 32 + u * 16 + g;
            const int r1 = r0 + 8;
            #pragma unroll
            for (int nt = 0; nt < 8; nt++) {
                #pragma unroll
                for (int i = 0; i < 4; i++) S[u][nt][i] *= scale;
            }
            if (j * 64 + 63 > q0 + w * 32 + u * 16) {
                #pragma unroll
                for (int nt = 0; nt < 8; nt++) {
                    int col = j * 64 + nt * 8 + 2 * lt;
                    if (col     > r0) S[u][nt][0] = -INFINITY;
                    if (col + 1 > r0) S[u][nt][1] = -INFINITY;
                    if (col     > r1) S[u][nt][2] = -INFINITY;
                    if (col + 1 > r1) S[u][nt][3] = -INFINITY;
                }
            }

            float mx0 = -INFINITY, mx1 = -INFINITY;
            #pragma unroll
            for (int nt = 0; nt < 8; nt++) {
                mx0 = fmaxf(mx0, fmaxf(S[u][nt][0], S[u][nt][1]));
                mx1 = fmaxf(mx1, fmaxf(S[u][nt][2], S[u][nt][3]));
            }
            mx0 = fmaxf(mx0, __shfl_xor_sync(0xffffffffu, mx0, 1));
            mx0 = fmaxf(mx0, __shfl_xor_sync(0xffffffffu, mx0, 2));
            mx1 = fmaxf(mx1, __shfl_xor_sync(0xffffffffu, mx1, 1));
            mx1 = fmaxf(mx1, __shfl_xor_sync(0xffffffffu, mx1, 2));
            float mn0 = fmaxf(mr[u][0], mx0);
            float mn1 = fmaxf(mr[u][1], mx1);
            float f0 = exp2f(mr[u][0] - mn0);
            float f1 = exp2f(mr[u][1] - mn1);
            mr[u][0] = mn0; mr[u][1] = mn1;

            float ps0 = 0.0f, ps1 = 0.0f;
            #pragma unroll
            for (int nt = 0; nt < 8; nt++) {
                float p0 = exp2f(S[u][nt][0] - mn0);
                float p1 = exp2f(S[u][nt][1] - mn0);
                float p2 = exp2f(S[u][nt][2] - mn1);
                float p3 = exp2f(S[u][nt][3] - mn1);
                ps0 += p0 + p1;
                ps1 += p2 + p3;
                Ptf[u][nt][0] = f2tf(p0); Ptf[u][nt][1] = f2tf(p1);
                Ptf[u][nt][2] = f2tf(p2); Ptf[u][nt][3] = f2tf(p3);
            }
            ps0 += __shfl_xor_sync(0xffffffffu, ps0, 1);
            ps0 += __shfl_xor_sync(0xffffffffu, ps0, 2);
            ps1 += __shfl_xor_sync(0xffffffffu, ps1, 1);
            ps1 += __shfl_xor_sync(0xffffffffu, ps1, 2);
            lr[u][0] = lr[u][0] * f0 + ps0;
            lr[u][1] = lr[u][1] * f1 + ps1;

            #pragma unroll
            for (int nt = 0; nt < 8; nt++) {
                O[u][nt][0] *= f0; O[u][nt][1] *= f0;
                O[u][nt][2] *= f1; O[u][nt][3] *= f1;
            }
        }

        // ---- O += P @ V : raw fp32 V fragments ----
        #pragma unroll
        for (int kt = 0; kt < 8; kt++) {
            uint32_t A[2][4];
            #pragma unroll
            for (int u = 0; u < 2; u++) {
                uint32_t pa0 = __shfl_sync(0xffffffffu, Ptf[u][kt][0], srcA);
                uint32_t pa1 = __shfl_sync(0xffffffffu, Ptf[u][kt][1], srcA);
                uint32_t pa2 = __shfl_sync(0xffffffffu, Ptf[u][kt][2], srcA);
                uint32_t pa3 = __shfl_sync(0xffffffffu, Ptf[u][kt][3], srcA);
                uint32_t pb0 = __shfl_sync(0xffffffffu, Ptf[u][kt][0], srcB);
                uint32_t pb1 = __shfl_sync(0xffffffffu, Ptf[u][kt][1], srcB);
                uint32_t pb2 = __shfl_sync(0xffffffffu, Ptf[u][kt][2], srcB);
                uint32_t pb3 = __shfl_sync(0xffffffffu, Ptf[u][kt][3], srcB);
                A[u][0] = par ? pa1 : pa0;
                A[u][1] = par ? pa3 : pa2;
                A[u][2] = par ? pb1 : pb0;
                A[u][3] = par ? pb3 : pb2;
            }
            const uint32_t* vrow0 = &sV[(kt * 8 + lt) * VSTR + g];
            const uint32_t* vrow1 = &sV[(kt * 8 + lt + 4) * VSTR + g];
            #pragma unroll
            for (int nt = 0; nt < 8; nt++) {
                uint32_t b0 = vrow0[nt * 8];
                uint32_t b1 = vrow1[nt * 8];
                mma_tf32(O[0][nt], A[0], b0, b1);
                mma_tf32(O[1][nt], A[1], b0, b1);
            }
        }
        __syncthreads();
    }

    // ---- write output ----
    #pragma unroll
    for (int u = 0; u < 2; u++) {
        const int r0 = q0 + w * 32 + u * 16 + g;
        const int r1 = r0 + 8;
        float inv0 = 1.0f / lr[u][0];
        float inv1 = 1.0f / lr[u][1];
        #pragma unroll
        for (int nt = 0; nt < 8; nt++) {
            int e = h * DHD + nt * 8 + 2 * lt;
            size_t o0 = ((size_t)b * SS + r0) * (HH * DHD) + e;
            size_t o1 = ((size_t)b * SS + r1) * (HH * DHD) + e;
            *(float2*)&out[o0] = make_float2(O[u][nt][0] * inv0, O[u][nt][1] * inv0);
            *(float2*)&out[o1] = make_float2(O[u][nt][2] * inv1, O[u][nt][3] * inv1);
        }
    }
}

extern "C" void kernel_launch(void* const* d_in, const int* in_sizes, int n_in,
                              void* d_out, int out_size) {
    const float* x  = (const float*)d_in[0];
    const float* Wq = (const float*)d_in[1];
    const float* Wk = (const float*)d_in[2];
    const float* Wv = (const float*)d_in[3];
    float* out = (float*)d_out;

    cudaFuncSetAttribute(qkv_proj_tc_kernel,
                         cudaFuncAttributeMaxDynamicSharedMemorySize,
                         PROJ_SMEM_BYTES);
    cudaFuncSetAttribute(flash_attn_tc_kernel,
                         cudaFuncAttributeMaxDynamicSharedMemorySize,
                         ATT_SMEM_BYTES);

    qkv_proj_tc_kernel<<<dim3(NROW / 64, HH), 128, PROJ_SMEM_BYTES>>>(x, Wq, Wk, Wv);
    flash_attn_tc_kernel<<<dim3(SS / 128, BB * HH), 128, ATT_SMEM_BYTES>>>(out);
}